// round 10
// baseline (speedup 1.0000x reference)
#include <cuda_runtime.h>
#include <cuda_bf16.h>
#include <cstdint>

#define NN 8192
#define IN_DIM 256
#define HID 128
#define PZ 136  // pitch bf16 for 128-col Zn tiles
#define PT 72   // pitch bf16 for 64-col tiles

// ---------------- k_pass2s smem layout (bf16-elem offsets / bytes) ---------
#define ZNH_E 0
#define ZNL_E (128 * PZ)
#define ZT_E(buf, hl) (2 * 128 * PZ + ((buf) * 2 + (hl)) * 128 * PT)
#define SST_BYTE ((2 * 128 * PZ + 4 * 128 * PT) * 2)       // 143360
#define SMEM_P2 (SST_BYTE + 128 * 65 * 4)                  // 176640

// ---------------- k_norm2 smem layout (byte offsets) -----------------------
#define ZT2_B(buf, hl) (((buf) * 2 + (hl)) * 128 * PT * 2) // 4 x 18432
#define SHI_B (4 * 128 * PT * 2)                           // 73728
#define SLO_B (SHI_B + 128 * PT * 2)                       // 92160
#define AU_B(buf) (SLO_B + 128 * PT * 2 + (buf) * 128 * 68 * 4)
#define SMEM_N2 (AU_B(2))                                  // 180224

// ---------------- device scratch (no cudaMalloc allowed) -------------------
__device__ __nv_bfloat16 g_Zhi[NN * HID];
__device__ __nv_bfloat16 g_Zlo[NN * HID];
__device__ __nv_bfloat16 g_ZThi[(long)HID * NN];
__device__ __nv_bfloat16 g_ZTlo[(long)HID * NN];
__device__ float g_outp[2 * NN * HID];  // per-column-half partial out
__device__ float g_rs[NN];              // global rowsum (atomic)

// ---------------- primitives (baseline PTX, no sm_103a gating) -------------
__device__ __forceinline__ uint32_t smem_u32(const void* p) {
    uint32_t a;
    asm("{ .reg .u64 t; cvta.to.shared.u64 t, %1; cvt.u32.u64 %0, t; }"
        : "=r"(a) : "l"(p));
    return a;
}
__device__ __forceinline__ void ldsm_x4(uint32_t* r, uint32_t addr) {
    asm volatile("ldmatrix.sync.aligned.m8n8.x4.shared.b16 {%0,%1,%2,%3}, [%4];"
                 : "=r"(r[0]), "=r"(r[1]), "=r"(r[2]), "=r"(r[3]) : "r"(addr));
}
__device__ __forceinline__ void ldsm_x4t(uint32_t* r, uint32_t addr) {
    asm volatile("ldmatrix.sync.aligned.m8n8.x4.trans.shared.b16 {%0,%1,%2,%3}, [%4];"
                 : "=r"(r[0]), "=r"(r[1]), "=r"(r[2]), "=r"(r[3]) : "r"(addr));
}
__device__ __forceinline__ void mma16816(float* c, const uint32_t* a,
                                         const uint32_t* b) {
    asm volatile(
        "mma.sync.aligned.m16n8k16.row.col.f32.bf16.bf16.f32 "
        "{%0,%1,%2,%3}, {%4,%5,%6,%7}, {%8,%9}, {%0,%1,%2,%3};"
        : "+f"(c[0]), "+f"(c[1]), "+f"(c[2]), "+f"(c[3])
        : "r"(a[0]), "r"(a[1]), "r"(a[2]), "r"(a[3]), "r"(b[0]), "r"(b[1]));
}
__device__ __forceinline__ void cp16(uint32_t dst, const void* src) {
    asm volatile("cp.async.cg.shared.global [%0], [%1], 16;"
                 :: "r"(dst), "l"(src));
}
#define CP_COMMIT() asm volatile("cp.async.commit_group;")
#define CP_WAIT1() asm volatile("cp.async.wait_group 1;")
#define CP_WAIT0() asm volatile("cp.async.wait_group 0;")
__device__ __forceinline__ void stcs2(float* p, float x, float y) {
    asm volatile("st.global.cs.v2.f32 [%0], {%1,%2};" :: "l"(p), "f"(x), "f"(y));
}
__device__ __forceinline__ uint32_t pack_bf2(float x, float y) {
    __nv_bfloat162 t;
    t.x = __float2bfloat16(x);
    t.y = __float2bfloat16(y);
    return *reinterpret_cast<uint32_t*>(&t);
}

// ---------------------------------------------------------------------------
// Phase 1: Z = X @ W^T (fp32), emit bf16 hi/lo + smem-staged transposed hi/lo
// Also zeroes g_rs (needed before k_pass2s atomics).
// ---------------------------------------------------------------------------
__global__ __launch_bounds__(256) void k_gemm_z(const float* __restrict__ X,
                                                const float* __restrict__ W) {
    __shared__ __align__(16) float pool[2 * 64 * 33];
    float* Xs = pool;
    float* Ws = pool + 64 * 33;
    const int tid = threadIdx.x;
    if (blockIdx.y == 0) {
        int gi = blockIdx.x * 256 + tid;
        if (gi < NN) g_rs[gi] = 0.0f;
    }
    const int tx = tid & 15, ty = tid >> 4;
    const int row0 = blockIdx.x * 64;
    const int col0 = blockIdx.y * 64;
    float acc[4][4] = {};

    for (int k0 = 0; k0 < IN_DIM; k0 += 32) {
        for (int idx = tid; idx < 64 * 32; idx += 256) {
            int r = idx >> 5, c = idx & 31;
            Xs[r * 33 + c] = X[(row0 + r) * IN_DIM + k0 + c];
            Ws[r * 33 + c] = W[(col0 + r) * IN_DIM + k0 + c];
        }
        __syncthreads();
#pragma unroll 8
        for (int k = 0; k < 32; k++) {
            float a[4], b[4];
#pragma unroll
            for (int i = 0; i < 4; i++) a[i] = Xs[(ty * 4 + i) * 33 + k];
#pragma unroll
            for (int j = 0; j < 4; j++) b[j] = Ws[(tx * 4 + j) * 33 + k];
#pragma unroll
            for (int i = 0; i < 4; i++)
#pragma unroll
                for (int j = 0; j < 4; j++) acc[i][j] = fmaf(a[i], b[j], acc[i][j]);
        }
        __syncthreads();
    }

    __nv_bfloat16 h4[4][4], l4[4][4];
#pragma unroll
    for (int i = 0; i < 4; i++)
#pragma unroll
        for (int j = 0; j < 4; j++) {
            int r = row0 + ty * 4 + i, c = col0 + tx * 4 + j;
            float v = acc[i][j];
            __nv_bfloat16 h = __float2bfloat16(v);
            __nv_bfloat16 l = __float2bfloat16(v - __bfloat162float(h));
            h4[i][j] = h; l4[i][j] = l;
            g_Zhi[r * HID + c] = h;
            g_Zlo[r * HID + c] = l;
        }

    __nv_bfloat16* tb = (__nv_bfloat16*)pool;
#pragma unroll
    for (int pass = 0; pass < 2; pass++) {
        __syncthreads();
#pragma unroll
        for (int i = 0; i < 4; i++)
#pragma unroll
            for (int j = 0; j < 4; j++)
                tb[(tx * 4 + j) * 72 + ty * 4 + i] = pass ? l4[i][j] : h4[i][j];
        __syncthreads();
        __nv_bfloat16* gp = pass ? g_ZTlo : g_ZThi;
#pragma unroll
        for (int k = 0; k < 2; k++) {
            int idx = tid + k * 256;
            int c_loc = idx >> 3;
            int r8 = (idx & 7) * 8;
            *(uint4*)&gp[(long)(col0 + c_loc) * NN + row0 + r8] =
                *(uint4*)&tb[c_loc * 72 + r8];
        }
    }
}

// ---------------------------------------------------------------------------
__device__ __forceinline__ void copy_tile_z(__nv_bfloat16* __restrict__ dst,
                                            const __nv_bfloat16* __restrict__ src,
                                            int tid) {
#pragma unroll
    for (int i = 0; i < 8; i++) {
        int idx = tid + i * 256;
        int row = idx >> 4;
        int c8 = (idx & 15) * 8;
        *(uint4*)&dst[row * PZ + c8] = *(const uint4*)&src[(long)row * HID + c8];
    }
}

// async copy one 128x64 Zt tile pair (hi+lo); byte bases given
__device__ __forceinline__ void issue_zt2(uint32_t smb, uint32_t baseH,
                                          uint32_t baseL, int m0, int tid) {
    const __nv_bfloat16* gh = g_ZThi + m0;
    const __nv_bfloat16* gl = g_ZTlo + m0;
#pragma unroll
    for (int i = 0; i < 4; i++) {
        int idx = tid + i * 256;
        int row = idx >> 3;
        int c8 = (idx & 7) * 8;
        uint32_t so = (uint32_t)(row * PT + c8) * 2;
        long go = (long)row * NN + c8;
        cp16(smb + baseH + so, gh + go);
        cp16(smb + baseL + so, gl + go);
    }
}

// tile schedule for pair p: s in [0,130): rb / 64-wide col tile jp
__device__ __forceinline__ void tile_of(int p, int s, int& rb, int& jp) {
    if (s < 128 - 2 * p) { rb = p; jp = 2 * p + s; }
    else { rb = 63 - p; jp = s - 2; }
}

// ---------------------------------------------------------------------------
// Phase 2 (symmetric GEMM1 only): S = relu(Zn @ Zm^T) on upper-triangle tiles.
// Writes A_ij direct + A_ji via fp32 smem transpose; rowsum via row sums +
// mirror column sums (atomicAdd g_rs).
// ---------------------------------------------------------------------------
__global__ __launch_bounds__(256, 1) void k_pass2s(float* __restrict__ A) {
    extern __shared__ __nv_bfloat16 sm[];
    float* Sst = (float*)((char*)sm + SST_BYTE);
    const uint32_t smb = smem_u32(sm);
    const int tid = threadIdx.x;
    const int lane = tid & 31, wid = tid >> 5;
    const int wm4 = wid & 3, wn2 = wid >> 2;
    const int g = lane >> 2, tq = lane & 3;
    const int l15 = lane & 15;
    const int hi8 = (lane >> 4) * 8;
    const int p = blockIdx.x >> 2, q = blockIdx.x & 3;
    const int s0 = (130 * q) / 4, s1 = (130 * (q + 1)) / 4;

    const uint32_t a1H = smb + (ZNH_E + (wm4 * 32 + l15) * PZ + hi8) * 2;
    const uint32_t a1L = smb + (ZNL_E + (wm4 * 32 + l15) * PZ + hi8) * 2;

    int cur_rb = -1, n0 = 0;
    float rs[2][2] = {};

    {   // prologue prefetch
        int rb0, jp0;
        tile_of(p, s0, rb0, jp0);
        issue_zt2(smb, (uint32_t)ZT_E(0, 0) * 2, (uint32_t)ZT_E(0, 1) * 2,
                  jp0 * 64, tid);
        CP_COMMIT();
    }

    for (int s = s0; s < s1; s++) {
        const int cur = (s - s0) & 1;
        int rb, jp;
        tile_of(p, s, rb, jp);
        const int m0 = jp * 64;
        if (s + 1 < s1) {
            int rbn, jpn;
            tile_of(p, s + 1, rbn, jpn);
            issue_zt2(smb, (uint32_t)ZT_E(cur ^ 1, 0) * 2,
                      (uint32_t)ZT_E(cur ^ 1, 1) * 2, jpn * 64, tid);
            CP_COMMIT();
            CP_WAIT1();
        } else {
            CP_WAIT0();
        }
        __syncthreads();

        if (rb != cur_rb) {
            if (cur_rb >= 0) {
#pragma unroll
                for (int mf = 0; mf < 2; mf++)
#pragma unroll
                    for (int h = 0; h < 2; h++) {
                        float v = rs[mf][h];
                        v += __shfl_xor_sync(~0u, v, 1);
                        v += __shfl_xor_sync(~0u, v, 2);
                        if (tq == 0)
                            atomicAdd(&g_rs[n0 + wm4 * 32 + mf * 16 + g + 8 * h], v);
                        rs[mf][h] = 0.0f;
                    }
            }
            cur_rb = rb;
            n0 = rb * 128;
            copy_tile_z(sm + ZNH_E, g_Zhi + (long)n0 * HID, tid);
            copy_tile_z(sm + ZNL_E, g_Zlo + (long)n0 * HID, tid);
            __syncthreads();
        }

        const uint32_t ztH = ZT_E(cur, 0), ztL = ZT_E(cur, 1);
        const uint32_t b1H = smb + (ztH + l15 * PT + wn2 * 32 + hi8) * 2;
        const uint32_t b1L = smb + (ztL + l15 * PT + wn2 * 32 + hi8) * 2;

        // ---- GEMM1: S(128x64) split-bf16 x3, frag-cached; warp 32x32 ----
        float cacc[2][4][4] = {};
#pragma unroll
        for (int k8 = 0; k8 < 8; k8++) {
            const int k0 = k8 * 16;
            uint32_t aH[2][4], aL[2][4], bH[2][4], bL[2][4];
#pragma unroll
            for (int mf = 0; mf < 2; mf++) {
                ldsm_x4(aH[mf], a1H + (mf * 16 * PZ + k0) * 2);
                ldsm_x4(aL[mf], a1L + (mf * 16 * PZ + k0) * 2);
            }
#pragma unroll
            for (int pr = 0; pr < 2; pr++) {
                ldsm_x4t(bH[pr], b1H + (k0 * PT + pr * 16) * 2);
                ldsm_x4t(bL[pr], b1L + (k0 * PT + pr * 16) * 2);
            }
#pragma unroll
            for (int mf = 0; mf < 2; mf++)
#pragma unroll
                for (int pr = 0; pr < 2; pr++) {
                    mma16816(cacc[mf][2 * pr], aH[mf], &bH[pr][0]);
                    mma16816(cacc[mf][2 * pr + 1], aH[mf], &bH[pr][2]);
                    mma16816(cacc[mf][2 * pr], aH[mf], &bL[pr][0]);
                    mma16816(cacc[mf][2 * pr + 1], aH[mf], &bL[pr][2]);
                    mma16816(cacc[mf][2 * pr], aL[mf], &bH[pr][0]);
                    mma16816(cacc[mf][2 * pr + 1], aL[mf], &bH[pr][2]);
                }
        }

        const bool diag = ((jp >> 1) == rb);

        // ---- epilogue: relu, row-sums, direct A write, fp32 stage ----
#pragma unroll
        for (int mf = 0; mf < 2; mf++) {
#pragma unroll
            for (int nf = 0; nf < 4; nf++) {
                float* c = cacc[mf][nf];
                float v0 = fmaxf(c[0], 0.f), v1 = fmaxf(c[1], 0.f);
                float v2 = fmaxf(c[2], 0.f), v3 = fmaxf(c[3], 0.f);
                rs[mf][0] += v0 + v1;
                rs[mf][1] += v2 + v3;
                const int lr = wm4 * 32 + mf * 16 + g;
                const int lc = wn2 * 32 + nf * 8 + 2 * tq;
                stcs2(&A[(long)(n0 + lr) * NN + m0 + lc], v0, v1);
                stcs2(&A[(long)(n0 + lr + 8) * NN + m0 + lc], v2, v3);
                if (!diag) {
                    Sst[lr * 65 + lc] = v0;
                    Sst[lr * 65 + lc + 1] = v1;
                    Sst[(lr + 8) * 65 + lc] = v2;
                    Sst[(lr + 8) * 65 + lc + 1] = v3;
                }
            }
        }
        __syncthreads();

        // ---- mirror: A_ji = S^T, plus column sums -> g_rs ----
        if (!diag) {
            const int m = tid >> 2;
            const int ng = (tid & 3) * 32;
            float csum = 0.f;
            float* dst = &A[(long)(m0 + m) * NN + n0 + ng];
#pragma unroll
            for (int k = 0; k < 8; k++) {
                float4 w;
                w.x = Sst[(ng + 4 * k + 0) * 65 + m];
                w.y = Sst[(ng + 4 * k + 1) * 65 + m];
                w.z = Sst[(ng + 4 * k + 2) * 65 + m];
                w.w = Sst[(ng + 4 * k + 3) * 65 + m];
                csum += (w.x + w.y) + (w.z + w.w);
                __stcs((float4*)(dst + 4 * k), w);
            }
            csum += __shfl_xor_sync(~0u, csum, 1);
            csum += __shfl_xor_sync(~0u, csum, 2);
            if ((tid & 3) == 0) atomicAdd(&g_rs[m0 + m], csum);
        }
    }

    // final rowsum flush
#pragma unroll
    for (int mf = 0; mf < 2; mf++)
#pragma unroll
        for (int h = 0; h < 2; h++) {
            float v = rs[mf][h];
            v += __shfl_xor_sync(~0u, v, 1);
            v += __shfl_xor_sync(~0u, v, 2);
            if (tq == 0)
                atomicAdd(&g_rs[n0 + wm4 * 32 + mf * 16 + g + 8 * h], v);
        }
}

// ---------------------------------------------------------------------------
// Phase 3 (fused): stream A tiles in; write normalized A; split tile to bf16
// hi/lo in smem and run GEMM2 (out partial) on it. Grid (2, 64).
// ---------------------------------------------------------------------------
__global__ __launch_bounds__(256, 1) void k_norm2(float* __restrict__ A) {
    extern __shared__ char smc[];
    const uint32_t smb = smem_u32(smc);
    const int tid = threadIdx.x;
    const int lane = tid & 31, wid = tid >> 5;
    const int wm = wid & 1, wn = wid >> 1;
    const int g = lane >> 2, tq = lane & 3;
    const int l15 = lane & 15;
    const int hi8 = (lane >> 4) * 8;
    const int cs = blockIdx.x;
    const int n0 = blockIdx.y * 128;

    // per-thread fixed row for convert phase
    const int cr = tid >> 1;
    const int cc0 = (tid & 1) * 32;
    const float inv = 1.0f / (g_rs[n0 + cr] + 1e-6f);

    const uint32_t aSH = smb + SHI_B + ((wm * 64 + l15) * PT + hi8) * 2;
    const uint32_t aSL = smb + SLO_B + ((wm * 64 + l15) * PT + hi8) * 2;
    const int b2row = wn * 32 + ((lane >> 4) & 1) * 8 + (lane & 7);
    const int b2off = ((lane >> 3) & 1) * 8;

    float oacc[4][4][4] = {};

    // prologue: tile 0
    {
        const int m0 = cs * 4096;
#pragma unroll
        for (int k = 0; k < 8; k++) {
            int idx = tid + k * 256;
            int row = idx >> 4;
            int cchunk = (idx & 15) * 4;
            cp16(smb + AU_B(0) + (uint32_t)(row * 68 + cchunk) * 4,
                 A + (long)(n0 + row) * NN + m0 + cchunk);
        }
        issue_zt2(smb, ZT2_B(0, 0), ZT2_B(0, 1), m0, tid);
        CP_COMMIT();
    }

    for (int t = 0; t < 64; t++) {
        const int cur = t & 1;
        const int m0 = cs * 4096 + t * 64;
        if (t < 63) {
            const int m0n = m0 + 64;
#pragma unroll
            for (int k = 0; k < 8; k++) {
                int idx = tid + k * 256;
                int row = idx >> 4;
                int cchunk = (idx & 15) * 4;
                cp16(smb + AU_B(cur ^ 1) + (uint32_t)(row * 68 + cchunk) * 4,
                     A + (long)(n0 + row) * NN + m0n + cchunk);
            }
            issue_zt2(smb, ZT2_B(cur ^ 1, 0), ZT2_B(cur ^ 1, 1), m0n, tid);
            CP_COMMIT();
            CP_WAIT1();
        } else {
            CP_WAIT0();
        }
        __syncthreads();

        // ---- convert: normalized A write + bf16 hi/lo split to smem ----
        {
            const float* au = (const float*)(smc + AU_B(cur)) + cr * 68 + cc0;
            float* arow = A + (long)(n0 + cr) * NN + m0 + cc0;
            char* shi = smc + SHI_B + (cr * PT + cc0) * 2;
            char* slo = smc + SLO_B + (cr * PT + cc0) * 2;
#pragma unroll
            for (int j = 0; j < 32; j += 4) {
                float4 v = *(const float4*)(au + j);
                float hx = __bfloat162float(__float2bfloat16(v.x));
                float hy = __bfloat162float(__float2bfloat16(v.y));
                float hz = __bfloat162float(__float2bfloat16(v.z));
                float hw = __bfloat162float(__float2bfloat16(v.w));
                *(uint32_t*)(shi + j * 2) = pack_bf2(v.x, v.y);
                *(uint32_t*)(shi + j * 2 + 4) = pack_bf2(v.z, v.w);
                *(uint32_t*)(slo + j * 2) = pack_bf2(v.x - hx, v.y - hy);
                *(uint32_t*)(slo + j * 2 + 4) = pack_bf2(v.z - hz, v.w - hw);
                float4 w = make_float4(v.x * inv, v.y * inv, v.z * inv, v.w * inv);
                __stcs((float4*)(arow + j), w);
            }
        }
        __syncthreads();

        // ---- GEMM2: out += S(split) @ Zt-as-B(split); warp 64x32 ----
        const uint32_t b2H = smb + ZT2_B(cur, 0) + (uint32_t)(b2row * PT + b2off) * 2;
        const uint32_t b2L = smb + ZT2_B(cur, 1) + (uint32_t)(b2row * PT + b2off) * 2;
#pragma unroll
        for (int k8 = 0; k8 < 4; k8++) {
            const int k0 = k8 * 16;
            uint32_t aH[4][4], aL[4][4], bH[2][4], bL[2][4];
#pragma unroll
            for (int mf = 0; mf < 4; mf++) {
                ldsm_x4(aH[mf], aSH + (mf * 16 * PT + k0) * 2);
                ldsm_x4(aL[mf], aSL + (mf * 16 * PT + k0) * 2);
            }
#pragma unroll
            for (int pr = 0; pr < 2; pr++) {
                ldsm_x4(bH[pr], b2H + (pr * 16 * PT + k0) * 2);
                ldsm_x4(bL[pr], b2L + (pr * 16 * PT + k0) * 2);
            }
#pragma unroll
            for (int mf = 0; mf < 4; mf++)
#pragma unroll
                for (int pr = 0; pr < 2; pr++) {
                    mma16816(oacc[mf][2 * pr], aH[mf], &bH[pr][0]);
                    mma16816(oacc[mf][2 * pr + 1], aH[mf], &bH[pr][2]);
                    mma16816(oacc[mf][2 * pr], aH[mf], &bL[pr][0]);
                    mma16816(oacc[mf][2 * pr + 1], aH[mf], &bL[pr][2]);
                    mma16816(oacc[mf][2 * pr], aL[mf], &bH[pr][0]);
                    mma16816(oacc[mf][2 * pr + 1], aL[mf], &bH[pr][2]);
                }
        }
        __syncthreads();  // Zt[cur]/SHI reuse guard
    }

    // ---- out partial stores ----
    float* op = g_outp + (long)cs * NN * HID;
#pragma unroll
    for (int mf = 0; mf < 4; mf++)
#pragma unroll
        for (int nf = 0; nf < 4; nf++) {
            const int r0 = n0 + wm * 64 + mf * 16 + g;
            const int col = wn * 32 + nf * 8 + 2 * tq;
            *(float2*)&op[r0 * HID + col] =
                make_float2(oacc[mf][nf][0], oacc[mf][nf][1]);
            *(float2*)&op[(r0 + 8) * HID + col] =
                make_float2(oacc[mf][nf][2], oacc[mf][nf][3]);
        }
}

// ---------------------------------------------------------------------------
// Phase 3b: out = (partial0 + partial1) * inv(rowsum)
// ---------------------------------------------------------------------------
__global__ void k_norm_out(float* __restrict__ o) {
    int i = blockIdx.x * blockDim.x + threadIdx.x;
    if (i < NN * HID) {
        int r = i >> 7;
        float inv = 1.0f / (g_rs[r] + 1e-6f);
        o[i] = (g_outp[i] + g_outp[NN * HID + i]) * inv;
    }
}

// ---------------------------------------------------------------------------
extern "C" void kernel_launch(void* const* d_in, const int* in_sizes, int n_in,
                              void* d_out, int out_size) {
    const float* X = (const float*)d_in[0];
    const float* W = (const float*)d_in[1];
    float* out = (float*)d_out;
    float* A = out + NN * HID;

    k_gemm_z<<<dim3(NN / 64, HID / 64), 256>>>(X, W);

    cudaFuncSetAttribute(k_pass2s, cudaFuncAttributeMaxDynamicSharedMemorySize,
                         SMEM_P2);
    k_pass2s<<<128, 256, SMEM_P2>>>(A);

    cudaFuncSetAttribute(k_norm2, cudaFuncAttributeMaxDynamicSharedMemorySize,
                         SMEM_N2);
    k_norm2<<<dim3(2, 64), 256, SMEM_N2>>>(A);

    k_norm_out<<<(NN * HID + 255) / 256, 256>>>(out);
}

// round 11
// speedup vs baseline: 1.1820x; 1.1820x over previous
#include <cuda_runtime.h>
#include <cuda_bf16.h>
#include <cstdint>

#define NN 8192
#define IN_DIM 256
#define HID 128
#define PZ 136  // pitch bf16 for 128-col tiles (odd 16B stride)
#define PT 72   // pitch bf16 for 64-col tiles (odd 16B stride)

// smem element offsets (bf16)
#define ZNH_E 0
#define ZNL_E (128 * PZ)
#define ZT_E(buf, hl) (2 * 128 * PZ + ((buf) * 2 + (hl)) * 128 * PT)  // buf 0..2
#define SHI_E (2 * 128 * PZ + 6 * 128 * PT)
#define SLO_E (SHI_E + 128 * PT)
#define SMEM_BYTES ((SLO_E + 128 * PT) * 2)  // 217088

// ---------------- device scratch (no cudaMalloc allowed) -------------------
__device__ __nv_bfloat16 g_Zhi[NN * HID];
__device__ __nv_bfloat16 g_Zlo[NN * HID];
__device__ __nv_bfloat16 g_ZThi[(long)HID * NN];
__device__ __nv_bfloat16 g_ZTlo[(long)HID * NN];
__device__ float g_outp[2 * NN * HID];  // per-column-half partial out
__device__ float g_rs[2 * NN];          // per-column-half partial rowsum

// ---------------- primitives (baseline PTX, no sm_103a gating) -------------
__device__ __forceinline__ uint32_t smem_u32(const void* p) {
    uint32_t a;
    asm("{ .reg .u64 t; cvta.to.shared.u64 t, %1; cvt.u32.u64 %0, t; }"
        : "=r"(a) : "l"(p));
    return a;
}
__device__ __forceinline__ void ldsm_x4(uint32_t* r, uint32_t addr) {
    asm volatile("ldmatrix.sync.aligned.m8n8.x4.shared.b16 {%0,%1,%2,%3}, [%4];"
                 : "=r"(r[0]), "=r"(r[1]), "=r"(r[2]), "=r"(r[3]) : "r"(addr));
}
__device__ __forceinline__ void ldsm_x4t(uint32_t* r, uint32_t addr) {
    asm volatile("ldmatrix.sync.aligned.m8n8.x4.trans.shared.b16 {%0,%1,%2,%3}, [%4];"
                 : "=r"(r[0]), "=r"(r[1]), "=r"(r[2]), "=r"(r[3]) : "r"(addr));
}
__device__ __forceinline__ void mma16816(float* c, const uint32_t* a,
                                         const uint32_t* b) {
    asm volatile(
        "mma.sync.aligned.m16n8k16.row.col.f32.bf16.bf16.f32 "
        "{%0,%1,%2,%3}, {%4,%5,%6,%7}, {%8,%9}, {%0,%1,%2,%3};"
        : "+f"(c[0]), "+f"(c[1]), "+f"(c[2]), "+f"(c[3])
        : "r"(a[0]), "r"(a[1]), "r"(a[2]), "r"(a[3]), "r"(b[0]), "r"(b[1]));
}
__device__ __forceinline__ void cp16(uint32_t dst, const void* src) {
    asm volatile("cp.async.cg.shared.global [%0], [%1], 16;"
                 :: "r"(dst), "l"(src));
}
#define CP_COMMIT() asm volatile("cp.async.commit_group;")
#define CP_WAIT1() asm volatile("cp.async.wait_group 1;")
#define CP_WAIT0() asm volatile("cp.async.wait_group 0;")
__device__ __forceinline__ void stcs2(float* p, float x, float y) {
    asm volatile("st.global.cs.v2.f32 [%0], {%1,%2};" :: "l"(p), "f"(x), "f"(y));
}
__device__ __forceinline__ uint32_t pack_bf2(float x, float y) {
    __nv_bfloat162 t;
    t.x = __float2bfloat16(x);
    t.y = __float2bfloat16(y);
    return *reinterpret_cast<uint32_t*>(&t);
}

// ---------------------------------------------------------------------------
// Phase 1: Z = X @ W^T (fp32), emit bf16 hi/lo + smem-staged transposed hi/lo
// ---------------------------------------------------------------------------
__global__ __launch_bounds__(256) void k_gemm_z(const float* __restrict__ X,
                                                const float* __restrict__ W) {
    __shared__ __align__(16) float pool[2 * 64 * 33];
    float* Xs = pool;
    float* Ws = pool + 64 * 33;
    const int tid = threadIdx.x;
    const int tx = tid & 15, ty = tid >> 4;
    const int row0 = blockIdx.x * 64;
    const int col0 = blockIdx.y * 64;
    float acc[4][4] = {};

    for (int k0 = 0; k0 < IN_DIM; k0 += 32) {
        for (int idx = tid; idx < 64 * 32; idx += 256) {
            int r = idx >> 5, c = idx & 31;
            Xs[r * 33 + c] = X[(row0 + r) * IN_DIM + k0 + c];
            Ws[r * 33 + c] = W[(col0 + r) * IN_DIM + k0 + c];
        }
        __syncthreads();
#pragma unroll 8
        for (int k = 0; k < 32; k++) {
            float a[4], b[4];
#pragma unroll
            for (int i = 0; i < 4; i++) a[i] = Xs[(ty * 4 + i) * 33 + k];
#pragma unroll
            for (int j = 0; j < 4; j++) b[j] = Ws[(tx * 4 + j) * 33 + k];
#pragma unroll
            for (int i = 0; i < 4; i++)
#pragma unroll
                for (int j = 0; j < 4; j++) acc[i][j] = fmaf(a[i], b[j], acc[i][j]);
        }
        __syncthreads();
    }

    __nv_bfloat16 h4[4][4], l4[4][4];
#pragma unroll
    for (int i = 0; i < 4; i++)
#pragma unroll
        for (int j = 0; j < 4; j++) {
            int r = row0 + ty * 4 + i, c = col0 + tx * 4 + j;
            float v = acc[i][j];
            __nv_bfloat16 h = __float2bfloat16(v);
            __nv_bfloat16 l = __float2bfloat16(v - __bfloat162float(h));
            h4[i][j] = h; l4[i][j] = l;
            g_Zhi[r * HID + c] = h;
            g_Zlo[r * HID + c] = l;
        }

    __nv_bfloat16* tb = (__nv_bfloat16*)pool;
#pragma unroll
    for (int pass = 0; pass < 2; pass++) {
        __syncthreads();
#pragma unroll
        for (int i = 0; i < 4; i++)
#pragma unroll
            for (int j = 0; j < 4; j++)
                tb[(tx * 4 + j) * 72 + ty * 4 + i] = pass ? l4[i][j] : h4[i][j];
        __syncthreads();
        __nv_bfloat16* gp = pass ? g_ZTlo : g_ZThi;
#pragma unroll
        for (int k = 0; k < 2; k++) {
            int idx = tid + k * 256;
            int c_loc = idx >> 3;
            int r8 = (idx & 7) * 8;
            *(uint4*)&gp[(long)(col0 + c_loc) * NN + row0 + r8] =
                *(uint4*)&tb[c_loc * 72 + r8];
        }
    }
}

// ---------------------------------------------------------------------------
__device__ __forceinline__ void copy_tile_z(__nv_bfloat16* __restrict__ dst,
                                            const __nv_bfloat16* __restrict__ src,
                                            int tid) {
#pragma unroll
    for (int i = 0; i < 8; i++) {
        int idx = tid + i * 256;
        int row = idx >> 4;
        int c8 = (idx & 15) * 8;
        *(uint4*)&dst[row * PZ + c8] = *(const uint4*)&src[(long)row * HID + c8];
    }
}

// issue async copy of one 128x64 Zt tile pair (hi+lo) into buffer buf (0..2)
__device__ __forceinline__ void issue_zt(uint32_t smb, int buf, int m0, int tid) {
    const __nv_bfloat16* gh = g_ZThi + m0;
    const __nv_bfloat16* gl = g_ZTlo + m0;
    const uint32_t dH = smb + ZT_E(buf, 0) * 2;
    const uint32_t dL = smb + ZT_E(buf, 1) * 2;
#pragma unroll
    for (int i = 0; i < 4; i++) {
        int idx = tid + i * 256;
        int row = idx >> 3;
        int c8 = (idx & 7) * 8;
        uint32_t so = (uint32_t)(row * PT + c8) * 2;
        long go = (long)row * NN + c8;
        cp16(dH + so, gh + go);
        cp16(dL + so, gl + go);
    }
}

// ---------------------------------------------------------------------------
// Phase 2 (HMMA): CTA = 128-row block x half columns; 64 m-tiles of 64.
// Triple-buffered cp.async Zt (2 barriers/iter); Zn-hi fragments register-
// resident across all iterations; split-bf16 x3 GEMMs, frag-cached.
// GEMM1 warps (4m,2n) 32x32; GEMM2 warps (2m,4n) 64x32.
// ---------------------------------------------------------------------------
__global__ __launch_bounds__(256, 1) void k_pass2(float* __restrict__ A) {
    extern __shared__ __nv_bfloat16 sm[];
    __shared__ float red[128];
    const uint32_t smb = smem_u32(sm);
    const int tid = threadIdx.x;
    const int wid = tid >> 5, lane = tid & 31;
    const int wm = wid & 1, wn = wid >> 1;      // GEMM2 layout (2m,4n)
    const int wm4 = wid & 3, wn2 = wid >> 2;    // GEMM1 layout (4m,2n)
    const int g = lane >> 2, tq = lane & 3;
    const int l15 = lane & 15;
    const int hi8 = (lane >> 4) * 8;
    const int n0 = blockIdx.y * 128;
    const int cs = blockIdx.x;

    // prologue: prefetch Zt slots 0 and 1
    issue_zt(smb, 0, cs * 4096, tid);
    CP_COMMIT();
    issue_zt(smb, 1, cs * 4096 + 64, tid);
    CP_COMMIT();

    copy_tile_z(sm + ZNH_E, g_Zhi + (long)n0 * HID, tid);
    copy_tile_z(sm + ZNL_E, g_Zlo + (long)n0 * HID, tid);
    __syncthreads();

    // GEMM1 A frag bases
    const uint32_t a1H = smb + (ZNH_E + (wm4 * 32 + l15) * PZ + hi8) * 2;
    const uint32_t a1L = smb + (ZNL_E + (wm4 * 32 + l15) * PZ + hi8) * 2;
    // GEMM2 A frags (S)
    const uint32_t aSH = smb + (SHI_E + (wm * 64 + l15) * PT + hi8) * 2;
    const uint32_t aSL = smb + (SLO_E + (wm * 64 + l15) * PT + hi8) * 2;
    const int b2row = wn * 32 + ((lane >> 4) & 1) * 8 + (lane & 7);
    const int b2off = ((lane >> 3) & 1) * 8;

    // resident Zn-hi fragments (invariant across the whole m-loop)
    uint32_t rAH[2][8][4];
#pragma unroll
    for (int mf = 0; mf < 2; mf++)
#pragma unroll
        for (int k8 = 0; k8 < 8; k8++)
            ldsm_x4(rAH[mf][k8], a1H + (mf * 16 * PZ + k8 * 16) * 2);

    float oacc[4][4][4] = {};
    float rs[2][2] = {};

    for (int t = 0; t < 64; t++) {
        const int cur = t % 3;
        const int m0 = cs * 4096 + t * 64;
        if (t < 63) CP_WAIT1(); else CP_WAIT0();
        __syncthreads();
        if (t + 2 < 64) {  // safe: all warps past GEMM2(t-1) (read slot (t+2)%3)
            issue_zt(smb, (t + 2) % 3, m0 + 128, tid);
            CP_COMMIT();
        }

        const uint32_t ztH = ZT_E(cur, 0), ztL = ZT_E(cur, 1);
        const uint32_t b1H = smb + (ztH + l15 * PT + wn2 * 32 + hi8) * 2;
        const uint32_t b1L = smb + (ztL + l15 * PT + wn2 * 32 + hi8) * 2;
        const uint32_t b2H = smb + (ztH + b2row * PT + b2off) * 2;
        const uint32_t b2L = smb + (ztL + b2row * PT + b2off) * 2;

        // ---- GEMM1: S(128x64) = Zn(split) @ Zt(split); warp 32x32 ----
        float cacc[2][4][4] = {};
#pragma unroll
        for (int k8 = 0; k8 < 8; k8++) {
            const int k0 = k8 * 16;
            uint32_t aL[2][4], bH[2][4], bL[2][4];
#pragma unroll
            for (int mf = 0; mf < 2; mf++)
                ldsm_x4(aL[mf], a1L + (mf * 16 * PZ + k0) * 2);
#pragma unroll
            for (int pr = 0; pr < 2; pr++) {
                ldsm_x4t(bH[pr], b1H + (k0 * PT + pr * 16) * 2);
                ldsm_x4t(bL[pr], b1L + (k0 * PT + pr * 16) * 2);
            }
#pragma unroll
            for (int mf = 0; mf < 2; mf++)
#pragma unroll
                for (int pr = 0; pr < 2; pr++) {
                    mma16816(cacc[mf][2 * pr], rAH[mf][k8], &bH[pr][0]);
                    mma16816(cacc[mf][2 * pr + 1], rAH[mf][k8], &bH[pr][2]);
                    mma16816(cacc[mf][2 * pr], rAH[mf][k8], &bL[pr][0]);
                    mma16816(cacc[mf][2 * pr + 1], rAH[mf][k8], &bL[pr][2]);
                    mma16816(cacc[mf][2 * pr], aL[mf], &bH[pr][0]);
                    mma16816(cacc[mf][2 * pr + 1], aL[mf], &bH[pr][2]);
                }
        }

        // ---- epilogue: relu, rowsum, streaming A store, S->smem hi/lo ----
#pragma unroll
        for (int mf = 0; mf < 2; mf++) {
#pragma unroll
            for (int nf = 0; nf < 4; nf++) {
                float* c = cacc[mf][nf];
                float v0 = fmaxf(c[0], 0.f), v1 = fmaxf(c[1], 0.f);
                float v2 = fmaxf(c[2], 0.f), v3 = fmaxf(c[3], 0.f);
                rs[mf][0] += v0 + v1;
                rs[mf][1] += v2 + v3;
                const int lr = wm4 * 32 + mf * 16 + g;
                const int lc = wn2 * 32 + nf * 8 + 2 * tq;
                stcs2(&A[(long)(n0 + lr) * NN + m0 + lc], v0, v1);
                stcs2(&A[(long)(n0 + lr + 8) * NN + m0 + lc], v2, v3);
                float h0 = __bfloat162float(__float2bfloat16(v0));
                float h1 = __bfloat162float(__float2bfloat16(v1));
                float h2 = __bfloat162float(__float2bfloat16(v2));
                float h3 = __bfloat162float(__float2bfloat16(v3));
                *(uint32_t*)&sm[SHI_E + lr * PT + lc] = pack_bf2(v0, v1);
                *(uint32_t*)&sm[SLO_E + lr * PT + lc] = pack_bf2(v0 - h0, v1 - h1);
                *(uint32_t*)&sm[SHI_E + (lr + 8) * PT + lc] = pack_bf2(v2, v3);
                *(uint32_t*)&sm[SLO_E + (lr + 8) * PT + lc] = pack_bf2(v2 - h2, v3 - h3);
            }
        }
        __syncthreads();

        // ---- GEMM2: out(128x128) += S(split) @ Zt-as-B(split); warp 64x32 ----
#pragma unroll
        for (int k8 = 0; k8 < 4; k8++) {
            const int k0 = k8 * 16;
            uint32_t aH[4][4], aL[4][4], bH[2][4], bL[2][4];
#pragma unroll
            for (int mf = 0; mf < 4; mf++) {
                ldsm_x4(aH[mf], aSH + (mf * 16 * PT + k0) * 2);
                ldsm_x4(aL[mf], aSL + (mf * 16 * PT + k0) * 2);
            }
#pragma unroll
            for (int pr = 0; pr < 2; pr++) {
                ldsm_x4(bH[pr], b2H + (pr * 16 * PT + k0) * 2);
                ldsm_x4(bL[pr], b2L + (pr * 16 * PT + k0) * 2);
            }
#pragma unroll
            for (int mf = 0; mf < 4; mf++)
#pragma unroll
                for (int pr = 0; pr < 2; pr++) {
                    mma16816(oacc[mf][2 * pr], aH[mf], &bH[pr][0]);
                    mma16816(oacc[mf][2 * pr + 1], aH[mf], &bH[pr][2]);
                    mma16816(oacc[mf][2 * pr], aH[mf], &bL[pr][0]);
                    mma16816(oacc[mf][2 * pr + 1], aH[mf], &bL[pr][2]);
                    mma16816(oacc[mf][2 * pr], aL[mf], &bH[pr][0]);
                    mma16816(oacc[mf][2 * pr + 1], aL[mf], &bH[pr][2]);
                }
        }
        // no trailing barrier: next iter's top barrier guards S reuse; Zt slot
        // for the next cp.async differs from all slots still being read.
    }

    // ---- rowsum: quad shuffle -> smem -> partial buffer ----
    if (tid < 128) red[tid] = 0.0f;
    __syncthreads();
#pragma unroll
    for (int mf = 0; mf < 2; mf++)
#pragma unroll
        for (int h = 0; h < 2; h++) {
            float v = rs[mf][h];
            v += __shfl_xor_sync(~0u, v, 1);
            v += __shfl_xor_sync(~0u, v, 2);
            if (tq == 0) atomicAdd(&red[wm4 * 32 + mf * 16 + g + 8 * h], v);
        }
    __syncthreads();
    if (tid < 128) g_rs[cs * NN + n0 + tid] = red[tid];

    // ---- out partial: direct stores ----
    float* op = g_outp + (long)cs * NN * HID;
#pragma unroll
    for (int mf = 0; mf < 4; mf++)
#pragma unroll
        for (int nf = 0; nf < 4; nf++) {
            const int r0 = n0 + wm * 64 + mf * 16 + g;
            const int col = wn * 32 + nf * 8 + 2 * tq;
            *(float2*)&op[r0 * HID + col] = make_float2(oacc[mf][nf][0], oacc[mf][nf][1]);
            *(float2*)&op[(r0 + 8) * HID + col] = make_float2(oacc[mf][nf][2], oacc[mf][nf][3]);
        }
}

// ---------------------------------------------------------------------------
// Phase 3a: A *= 1/(rowsum+1e-6); streaming, 4 independent float4 per thread
// ---------------------------------------------------------------------------
__global__ __launch_bounds__(256) void k_norm_A(float* __restrict__ A) {
    const long i0 = (long)blockIdx.x * 1024 + threadIdx.x;
    float4 v[4];
    float inv[4];
#pragma unroll
    for (int j = 0; j < 4; j++) {
        long i = i0 + j * 256;
        v[j] = __ldcs(&((const float4*)A)[i]);
        int r = (int)(i >> 11);
        inv[j] = 1.0f / (g_rs[r] + g_rs[NN + r] + 1e-6f);
    }
#pragma unroll
    for (int j = 0; j < 4; j++) {
        long i = i0 + j * 256;
        float4 w = v[j];
        w.x *= inv[j]; w.y *= inv[j]; w.z *= inv[j]; w.w *= inv[j];
        __stcs(&((float4*)A)[i], w);
    }
}

// ---------------------------------------------------------------------------
// Phase 3b: out = (partial0 + partial1) * inv(rowsum)
// ---------------------------------------------------------------------------
__global__ void k_norm_out(float* __restrict__ o) {
    int i = blockIdx.x * blockDim.x + threadIdx.x;
    if (i < NN * HID) {
        int r = i >> 7;
        float inv = 1.0f / (g_rs[r] + g_rs[NN + r] + 1e-6f);
        o[i] = (g_outp[i] + g_outp[NN * HID + i]) * inv;
    }
}

// ---------------------------------------------------------------------------
extern "C" void kernel_launch(void* const* d_in, const int* in_sizes, int n_in,
                              void* d_out, int out_size) {
    const float* X = (const float*)d_in[0];
    const float* W = (const float*)d_in[1];
    float* out = (float*)d_out;
    float* A = out + NN * HID;

    k_gemm_z<<<dim3(NN / 64, HID / 64), 256>>>(X, W);

    cudaFuncSetAttribute(k_pass2, cudaFuncAttributeMaxDynamicSharedMemorySize,
                         SMEM_BYTES);
    k_pass2<<<dim3(2, NN / 128), 256, SMEM_BYTES>>>(A);

    k_norm_A<<<16384, 256>>>(A);
    k_norm_out<<<(NN * HID + 255) / 256, 256>>>(out);
}

// round 14
// speedup vs baseline: 1.2310x; 1.0415x over previous
#include <cuda_runtime.h>
#include <cuda_bf16.h>
#include <cstdint>

#define NN 8192
#define IN_DIM 256
#define HID 128
#define PZ 136  // pitch bf16, 128-col tiles (odd 16B stride)
#define PT 72   // pitch bf16, 64-col tiles (odd 16B stride)

// smem element offsets (bf16)
#define ZNH_E 0
#define ZNL_E (128 * PZ)
#define ZT_E(buf, hl) (2 * 128 * PZ + ((buf) * 2 + (hl)) * 128 * PT)  // buf 0..2
#define SMEM_BYTES ((2 * 128 * PZ + 6 * 128 * PT) * 2)  // 180224

// ---------------- device scratch (no cudaMalloc allowed) -------------------
__device__ __nv_bfloat16 g_Zhi[NN * HID];
__device__ __nv_bfloat16 g_Zlo[NN * HID];
__device__ __nv_bfloat16 g_ZThi[(long)HID * NN];
__device__ __nv_bfloat16 g_ZTlo[(long)HID * NN];
__device__ float g_outp[2 * NN * HID];  // per-column-half partial out
__device__ float g_rs[2 * NN];          // per-column-half partial rowsum

// ---------------- primitives (baseline PTX, no sm_103a gating) -------------
__device__ __forceinline__ uint32_t smem_u32(const void* p) {
    uint32_t a;
    asm("{ .reg .u64 t; cvta.to.shared.u64 t, %1; cvt.u32.u64 %0, t; }"
        : "=r"(a) : "l"(p));
    return a;
}
__device__ __forceinline__ void ldsm_x4(uint32_t* r, uint32_t addr) {
    asm volatile("ldmatrix.sync.aligned.m8n8.x4.shared.b16 {%0,%1,%2,%3}, [%4];"
                 : "=r"(r[0]), "=r"(r[1]), "=r"(r[2]), "=r"(r[3]) : "r"(addr));
}
__device__ __forceinline__ void ldsm_x4t(uint32_t* r, uint32_t addr) {
    asm volatile("ldmatrix.sync.aligned.m8n8.x4.trans.shared.b16 {%0,%1,%2,%3}, [%4];"
                 : "=r"(r[0]), "=r"(r[1]), "=r"(r[2]), "=r"(r[3]) : "r"(addr));
}
__device__ __forceinline__ void mma16816(float* c, const uint32_t* a,
                                         const uint32_t* b) {
    asm volatile(
        "mma.sync.aligned.m16n8k16.row.col.f32.bf16.bf16.f32 "
        "{%0,%1,%2,%3}, {%4,%5,%6,%7}, {%8,%9}, {%0,%1,%2,%3};"
        : "+f"(c[0]), "+f"(c[1]), "+f"(c[2]), "+f"(c[3])
        : "r"(a[0]), "r"(a[1]), "r"(a[2]), "r"(a[3]), "r"(b[0]), "r"(b[1]));
}
__device__ __forceinline__ void cp16(uint32_t dst, const void* src) {
    asm volatile("cp.async.cg.shared.global [%0], [%1], 16;"
                 :: "r"(dst), "l"(src));
}
#define CP_COMMIT() asm volatile("cp.async.commit_group;")
#define CP_WAIT1() asm volatile("cp.async.wait_group 1;")
#define CP_WAIT0() asm volatile("cp.async.wait_group 0;")
__device__ __forceinline__ void stcs2(float* p, float x, float y) {
    asm volatile("st.global.cs.v2.f32 [%0], {%1,%2};" :: "l"(p), "f"(x), "f"(y));
}
__device__ __forceinline__ uint32_t pack_bf2(float x, float y) {
    __nv_bfloat162 t;
    t.x = __float2bfloat16(x);
    t.y = __float2bfloat16(y);
    return *reinterpret_cast<uint32_t*>(&t);
}

// ---------------------------------------------------------------------------
// Phase 1: Z = X @ W^T (fp32), emit bf16 hi/lo + smem-staged transposed hi/lo
// ---------------------------------------------------------------------------
__global__ __launch_bounds__(256) void k_gemm_z(const float* __restrict__ X,
                                                const float* __restrict__ W) {
    __shared__ __align__(16) float pool[2 * 64 * 33];
    float* Xs = pool;
    float* Ws = pool + 64 * 33;
    const int tid = threadIdx.x;
    const int tx = tid & 15, ty = tid >> 4;
    const int row0 = blockIdx.x * 64;
    const int col0 = blockIdx.y * 64;
    float acc[4][4] = {};

    for (int k0 = 0; k0 < IN_DIM; k0 += 32) {
        for (int idx = tid; idx < 64 * 32; idx += 256) {
            int r = idx >> 5, c = idx & 31;
            Xs[r * 33 + c] = X[(row0 + r) * IN_DIM + k0 + c];
            Ws[r * 33 + c] = W[(col0 + r) * IN_DIM + k0 + c];
        }
        __syncthreads();
#pragma unroll 8
        for (int k = 0; k < 32; k++) {
            float a[4], b[4];
#pragma unroll
            for (int i = 0; i < 4; i++) a[i] = Xs[(ty * 4 + i) * 33 + k];
#pragma unroll
            for (int j = 0; j < 4; j++) b[j] = Ws[(tx * 4 + j) * 33 + k];
#pragma unroll
            for (int i = 0; i < 4; i++)
#pragma unroll
                for (int j = 0; j < 4; j++) acc[i][j] = fmaf(a[i], b[j], acc[i][j]);
        }
        __syncthreads();
    }

    __nv_bfloat16 h4[4][4], l4[4][4];
#pragma unroll
    for (int i = 0; i < 4; i++)
#pragma unroll
        for (int j = 0; j < 4; j++) {
            int r = row0 + ty * 4 + i, c = col0 + tx * 4 + j;
            float v = acc[i][j];
            __nv_bfloat16 h = __float2bfloat16(v);
            __nv_bfloat16 l = __float2bfloat16(v - __bfloat162float(h));
            h4[i][j] = h; l4[i][j] = l;
            g_Zhi[r * HID + c] = h;
            g_Zlo[r * HID + c] = l;
        }

    __nv_bfloat16* tb = (__nv_bfloat16*)pool;
#pragma unroll
    for (int pass = 0; pass < 2; pass++) {
        __syncthreads();
#pragma unroll
        for (int i = 0; i < 4; i++)
#pragma unroll
            for (int j = 0; j < 4; j++)
                tb[(tx * 4 + j) * 72 + ty * 4 + i] = pass ? l4[i][j] : h4[i][j];
        __syncthreads();
        __nv_bfloat16* gp = pass ? g_ZTlo : g_ZThi;
#pragma unroll
        for (int k = 0; k < 2; k++) {
            int idx = tid + k * 256;
            int c_loc = idx >> 3;
            int r8 = (idx & 7) * 8;
            *(uint4*)&gp[(long)(col0 + c_loc) * NN + row0 + r8] =
                *(uint4*)&tb[c_loc * 72 + r8];
        }
    }
}

// ---------------------------------------------------------------------------
__device__ __forceinline__ void copy_tile_z(__nv_bfloat16* __restrict__ dst,
                                            const __nv_bfloat16* __restrict__ src,
                                            int tid) {
#pragma unroll
    for (int i = 0; i < 8; i++) {
        int idx = tid + i * 256;
        int row = idx >> 4;
        int c8 = (idx & 15) * 8;
        *(uint4*)&dst[row * PZ + c8] = *(const uint4*)&src[(long)row * HID + c8];
    }
}

// issue async copy of one 128x64 Zt tile pair (hi+lo) into buffer buf (0..2)
__device__ __forceinline__ void issue_zt(uint32_t smb, int buf, int m0, int tid) {
    const __nv_bfloat16* gh = g_ZThi + m0;
    const __nv_bfloat16* gl = g_ZTlo + m0;
    const uint32_t dH = smb + ZT_E(buf, 0) * 2;
    const uint32_t dL = smb + ZT_E(buf, 1) * 2;
#pragma unroll
    for (int i = 0; i < 4; i++) {
        int idx = tid + i * 256;
        int row = idx >> 3;
        int c8 = (idx & 7) * 8;
        uint32_t so = (uint32_t)(row * PT + c8) * 2;
        long go = (long)row * NN + c8;
        cp16(dH + so, gh + go);
        cp16(dL + so, gl + go);
    }
}

// ---------------------------------------------------------------------------
// Phase 2: register-resident S (FA2 style). Warp owns 16 S-rows x 64-col tile;
// S acc -> relu/split/pack in regs -> directly A-operand of GEMM2 (acc layout
// == A-frag layout). out[16x128] warp-private; 1 barrier/iter (Zt rotation).
// ---------------------------------------------------------------------------
__global__ __launch_bounds__(256, 1) void k_pass2(float* __restrict__ A) {
    extern __shared__ __nv_bfloat16 sm[];
    const uint32_t smb = smem_u32(sm);
    const int tid = threadIdx.x;
    const int wid = tid >> 5, lane = tid & 31;
    const int g = lane >> 2, tq = lane & 3;
    const int l15 = lane & 15;
    const int hi8 = (lane >> 4) * 8;
    const int n0 = blockIdx.y * 128;
    const int cs = blockIdx.x;

    // prologue: prefetch Zt slots 0,1
    issue_zt(smb, 0, cs * 4096, tid);
    CP_COMMIT();
    issue_zt(smb, 1, cs * 4096 + 64, tid);
    CP_COMMIT();

    copy_tile_z(sm + ZNH_E, g_Zhi + (long)n0 * HID, tid);
    copy_tile_z(sm + ZNL_E, g_Zlo + (long)n0 * HID, tid);
    __syncthreads();

    // resident Zn fragments: rows wid*16 + l15, all 8 k16-steps, hi & lo
    const uint32_t a1H = smb + (ZNH_E + (wid * 16 + l15) * PZ + hi8) * 2;
    const uint32_t a1L = smb + (ZNL_E + (wid * 16 + l15) * PZ + hi8) * 2;
    uint32_t rAH[8][4], rAL[8][4];
#pragma unroll
    for (int k8 = 0; k8 < 8; k8++) {
        ldsm_x4(rAH[k8], a1H + (k8 * 16) * 2);
        ldsm_x4(rAL[k8], a1L + (k8 * 16) * 2);
    }

    // GEMM2 B addressing (16x16 chunks, non-trans)
    const uint32_t b2off =
        (uint32_t)((((lane & 7) + ((lane >> 4) & 1) * 8) * PT +
                    ((lane >> 3) & 1) * 8) * 2);

    float oacc[16][4] = {};
    float rs0 = 0.0f, rs1 = 0.0f;

    for (int t = 0; t < 64; t++) {
        const int cur = t % 3;
        const int m0 = cs * 4096 + t * 64;
        if (t < 63) CP_WAIT1(); else CP_WAIT0();
        __syncthreads();  // Zt[cur] ready; all warps done with slot (t+2)%3
        if (t + 2 < 64) {
            issue_zt(smb, (t + 2) % 3, m0 + 128, tid);
            CP_COMMIT();
        }

        const uint32_t ztH = smb + ZT_E(cur, 0) * 2;
        const uint32_t ztL = smb + ZT_E(cur, 1) * 2;
        const uint32_t b1H = ztH + (uint32_t)(l15 * PT + hi8) * 2;
        const uint32_t b1L = ztL + (uint32_t)(l15 * PT + hi8) * 2;

        // ---- GEMM1: S[16x64] = Zn(split) @ Zt(split), A-frags resident ----
        float cacc[8][4] = {};
#pragma unroll
        for (int k8 = 0; k8 < 8; k8++) {
            uint32_t bH[4][4], bL[4][4];
#pragma unroll
            for (int nc = 0; nc < 4; nc++) {
                ldsm_x4t(bH[nc], b1H + (uint32_t)(k8 * 16 * PT + nc * 16) * 2);
                ldsm_x4t(bL[nc], b1L + (uint32_t)(k8 * 16 * PT + nc * 16) * 2);
            }
#pragma unroll
            for (int nc = 0; nc < 4; nc++) {
                mma16816(cacc[2 * nc], rAH[k8], &bH[nc][0]);
                mma16816(cacc[2 * nc + 1], rAH[k8], &bH[nc][2]);
                mma16816(cacc[2 * nc], rAH[k8], &bL[nc][0]);
                mma16816(cacc[2 * nc + 1], rAH[k8], &bL[nc][2]);
                mma16816(cacc[2 * nc], rAL[k8], &bH[nc][0]);
                mma16816(cacc[2 * nc + 1], rAL[k8], &bH[nc][2]);
            }
        }

        // ---- epilogue in registers: relu, rowsum, A store, pack S frags ----
        uint32_t aSH[4][4], aSL[4][4];
#pragma unroll
        for (int nf = 0; nf < 8; nf++) {
            float* c = cacc[nf];
            float v0 = fmaxf(c[0], 0.f), v1 = fmaxf(c[1], 0.f);
            float v2 = fmaxf(c[2], 0.f), v3 = fmaxf(c[3], 0.f);
            rs0 += v0 + v1;
            rs1 += v2 + v3;
            const int lr = wid * 16 + g;
            const int lc = nf * 8 + 2 * tq;
            stcs2(&A[(long)(n0 + lr) * NN + m0 + lc], v0, v1);
            stcs2(&A[(long)(n0 + lr + 8) * NN + m0 + lc], v2, v3);
            float h0 = __bfloat162float(__float2bfloat16(v0));
            float h1 = __bfloat162float(__float2bfloat16(v1));
            float h2 = __bfloat162float(__float2bfloat16(v2));
            float h3 = __bfloat162float(__float2bfloat16(v3));
            const int j = nf >> 1, half = (nf & 1) * 2;
            aSH[j][half + 0] = pack_bf2(v0, v1);
            aSH[j][half + 1] = pack_bf2(v2, v3);
            aSL[j][half + 0] = pack_bf2(v0 - h0, v1 - h1);
            aSL[j][half + 1] = pack_bf2(v2 - h2, v3 - h3);
        }

        // ---- GEMM2: out[16x128] += S(frag, split) @ Zt-as-B(split) ----
#pragma unroll
        for (int j = 0; j < 4; j++) {
#pragma unroll
            for (int nh = 0; nh < 8; nh++) {
                uint32_t bH2[4], bL2[4];
                const uint32_t boff = b2off + (uint32_t)(nh * 16 * PT + j * 16) * 2;
                ldsm_x4(bH2, ztH + boff);
                ldsm_x4(bL2, ztL + boff);
                mma16816(oacc[2 * nh], aSH[j], &bH2[0]);
                mma16816(oacc[2 * nh + 1], aSH[j], &bH2[2]);
                mma16816(oacc[2 * nh], aSH[j], &bL2[0]);
                mma16816(oacc[2 * nh + 1], aSH[j], &bL2[2]);
                mma16816(oacc[2 * nh], aSL[j], &bH2[0]);
                mma16816(oacc[2 * nh + 1], aSL[j], &bH2[2]);
            }
        }
    }

    // ---- rowsum: quad reduce, warp-private rows, direct store ----
    rs0 += __shfl_xor_sync(~0u, rs0, 1);
    rs0 += __shfl_xor_sync(~0u, rs0, 2);
    rs1 += __shfl_xor_sync(~0u, rs1, 1);
    rs1 += __shfl_xor_sync(~0u, rs1, 2);
    if (tq == 0) {
        g_rs[cs * NN + n0 + wid * 16 + g] = rs0;
        g_rs[cs * NN + n0 + wid * 16 + 8 + g] = rs1;
    }

    // ---- out partial: warp-private rows, direct stores ----
    float* op = g_outp + (long)cs * NN * HID;
    const int r0 = n0 + wid * 16 + g;
#pragma unroll
    for (int o = 0; o < 16; o++) {
        const int col = o * 8 + 2 * tq;
        *(float2*)&op[r0 * HID + col] = make_float2(oacc[o][0], oacc[o][1]);
        *(float2*)&op[(r0 + 8) * HID + col] = make_float2(oacc[o][2], oacc[o][3]);
    }
}

// ---------------------------------------------------------------------------
// Phase 3a: A *= 1/(rowsum+1e-6); streaming, 8 independent float4 per thread
// ---------------------------------------------------------------------------
__global__ __launch_bounds__(256) void k_norm_A(float* __restrict__ A) {
    const long i0 = (long)blockIdx.x * 2048 + threadIdx.x;
    float4 v[8];
    float inv[8];
#pragma unroll
    for (int j = 0; j < 8; j++) {
        long i = i0 + j * 256;
        v[j] = __ldcs(&((const float4*)A)[i]);
        int r = (int)(i >> 11);
        inv[j] = 1.0f / (g_rs[r] + g_rs[NN + r] + 1e-6f);
    }
#pragma unroll
    for (int j = 0; j < 8; j++) {
        long i = i0 + j * 256;
        float4 w = v[j];
        w.x *= inv[j]; w.y *= inv[j]; w.z *= inv[j]; w.w *= inv[j];
        __stcs(&((float4*)A)[i], w);
    }
}

// ---------------------------------------------------------------------------
// Phase 3b: out = (partial0 + partial1) * inv(rowsum)
// ---------------------------------------------------------------------------
__global__ void k_norm_out(float* __restrict__ o) {
    int i = blockIdx.x * blockDim.x + threadIdx.x;
    if (i < NN * HID) {
        int r = i >> 7;
        float inv = 1.0f / (g_rs[r] + g_rs[NN + r] + 1e-6f);
        o[i] = (g_outp[i] + g_outp[NN * HID + i]) * inv;
    }
}

// ---------------------------------------------------------------------------
extern "C" void kernel_launch(void* const* d_in, const int* in_sizes, int n_in,
                              void* d_out, int out_size) {
    const float* X = (const float*)d_in[0];
    const float* W = (const float*)d_in[1];
    float* out = (float*)d_out;
    float* A = out + NN * HID;

    k_gemm_z<<<dim3(NN / 64, HID / 64), 256>>>(X, W);

    cudaFuncSetAttribute(k_pass2, cudaFuncAttributeMaxDynamicSharedMemorySize,
                         SMEM_BYTES);
    k_pass2<<<dim3(2, NN / 128), 256, SMEM_BYTES>>>(A);

    k_norm_A<<<8192, 256>>>(A);
    k_norm_out<<<(NN * HID + 255) / 256, 256>>>(out);
}

// round 15
// speedup vs baseline: 1.2979x; 1.0543x over previous
#include <cuda_runtime.h>
#include <cuda_bf16.h>
#include <cstdint>

#define NN 8192
#define IN_DIM 256
#define HID 128
#define PZ 136  // pitch bf16, 128-col tiles (odd 16B stride)
#define PT 72   // pitch bf16, 64-col tiles (odd 16B stride)
#define NCTA 148
#define NTILE 8192  // 64 rowblocks x 128 col tiles

// smem element offsets (bf16)
#define ZNH_E 0
#define ZNL_E (128 * PZ)
#define ZT_E(buf, hl) (2 * 128 * PZ + ((buf) * 2 + (hl)) * 128 * PT)  // buf 0..2
#define SMEM_BYTES ((2 * 128 * PZ + 6 * 128 * PT) * 2)  // 180224

// ---------------- device scratch (no cudaMalloc allowed) -------------------
__device__ __nv_bfloat16 g_Zhi[NN * HID];
__device__ __nv_bfloat16 g_Zlo[NN * HID];
__device__ __nv_bfloat16 g_ZThi[(long)HID * NN];
__device__ __nv_bfloat16 g_ZTlo[(long)HID * NN];
__device__ float g_outp[NN * HID];  // atomically accumulated out partial
__device__ float g_rs[NN];          // atomically accumulated rowsum

// ---------------- primitives (baseline PTX, no sm_103a gating) -------------
__device__ __forceinline__ uint32_t smem_u32(const void* p) {
    uint32_t a;
    asm("{ .reg .u64 t; cvta.to.shared.u64 t, %1; cvt.u32.u64 %0, t; }"
        : "=r"(a) : "l"(p));
    return a;
}
__device__ __forceinline__ void ldsm_x4(uint32_t* r, uint32_t addr) {
    asm volatile("ldmatrix.sync.aligned.m8n8.x4.shared.b16 {%0,%1,%2,%3}, [%4];"
                 : "=r"(r[0]), "=r"(r[1]), "=r"(r[2]), "=r"(r[3]) : "r"(addr));
}
__device__ __forceinline__ void ldsm_x4t(uint32_t* r, uint32_t addr) {
    asm volatile("ldmatrix.sync.aligned.m8n8.x4.trans.shared.b16 {%0,%1,%2,%3}, [%4];"
                 : "=r"(r[0]), "=r"(r[1]), "=r"(r[2]), "=r"(r[3]) : "r"(addr));
}
__device__ __forceinline__ void mma16816(float* c, const uint32_t* a,
                                         const uint32_t* b) {
    asm volatile(
        "mma.sync.aligned.m16n8k16.row.col.f32.bf16.bf16.f32 "
        "{%0,%1,%2,%3}, {%4,%5,%6,%7}, {%8,%9}, {%0,%1,%2,%3};"
        : "+f"(c[0]), "+f"(c[1]), "+f"(c[2]), "+f"(c[3])
        : "r"(a[0]), "r"(a[1]), "r"(a[2]), "r"(a[3]), "r"(b[0]), "r"(b[1]));
}
__device__ __forceinline__ void cp16(uint32_t dst, const void* src) {
    asm volatile("cp.async.cg.shared.global [%0], [%1], 16;"
                 :: "r"(dst), "l"(src));
}
#define CP_COMMIT() asm volatile("cp.async.commit_group;")
#define CP_WAIT1() asm volatile("cp.async.wait_group 1;")
#define CP_WAIT0() asm volatile("cp.async.wait_group 0;")
__device__ __forceinline__ void stcs2(float* p, float x, float y) {
    asm volatile("st.global.cs.v2.f32 [%0], {%1,%2};" :: "l"(p), "f"(x), "f"(y));
}
__device__ __forceinline__ uint32_t pack_bf2(float x, float y) {
    __nv_bfloat162 t;
    t.x = __float2bfloat16(x);
    t.y = __float2bfloat16(y);
    return *reinterpret_cast<uint32_t*>(&t);
}

// ---------------------------------------------------------------------------
// Phase 1: Z = X @ W^T (fp32), emit bf16 hi/lo + smem-staged transposed hi/lo.
// Also zeroes g_outp and g_rs (needed before pass2 atomics).
// ---------------------------------------------------------------------------
__global__ __launch_bounds__(256) void k_gemm_z(const float* __restrict__ X,
                                                const float* __restrict__ W) {
    __shared__ __align__(16) float pool[2 * 64 * 33];
    float* Xs = pool;
    float* Ws = pool + 64 * 33;
    const int tid = threadIdx.x;
    const int flatb = blockIdx.y * gridDim.x + blockIdx.x;  // 0..255
    {   // zero accumulators: 256 blocks x 256 threads x 16 = 1,048,576
        float4 z4 = make_float4(0.f, 0.f, 0.f, 0.f);
        float4* op4 = (float4*)g_outp + (flatb * 256 + tid) * 4;
#pragma unroll
        for (int j = 0; j < 4; j++) op4[j] = z4;
        if (flatb < 32) g_rs[flatb * 256 + tid] = 0.0f;
    }
    const int tx = tid & 15, ty = tid >> 4;
    const int row0 = blockIdx.x * 64;
    const int col0 = blockIdx.y * 64;
    float acc[4][4] = {};

    for (int k0 = 0; k0 < IN_DIM; k0 += 32) {
        for (int idx = tid; idx < 64 * 32; idx += 256) {
            int r = idx >> 5, c = idx & 31;
            Xs[r * 33 + c] = X[(row0 + r) * IN_DIM + k0 + c];
            Ws[r * 33 + c] = W[(col0 + r) * IN_DIM + k0 + c];
        }
        __syncthreads();
#pragma unroll 8
        for (int k = 0; k < 32; k++) {
            float a[4], b[4];
#pragma unroll
            for (int i = 0; i < 4; i++) a[i] = Xs[(ty * 4 + i) * 33 + k];
#pragma unroll
            for (int j = 0; j < 4; j++) b[j] = Ws[(tx * 4 + j) * 33 + k];
#pragma unroll
            for (int i = 0; i < 4; i++)
#pragma unroll
                for (int j = 0; j < 4; j++) acc[i][j] = fmaf(a[i], b[j], acc[i][j]);
        }
        __syncthreads();
    }

    __nv_bfloat16 h4[4][4], l4[4][4];
#pragma unroll
    for (int i = 0; i < 4; i++)
#pragma unroll
        for (int j = 0; j < 4; j++) {
            int r = row0 + ty * 4 + i, c = col0 + tx * 4 + j;
            float v = acc[i][j];
            __nv_bfloat16 h = __float2bfloat16(v);
            __nv_bfloat16 l = __float2bfloat16(v - __bfloat162float(h));
            h4[i][j] = h; l4[i][j] = l;
            g_Zhi[r * HID + c] = h;
            g_Zlo[r * HID + c] = l;
        }

    __nv_bfloat16* tb = (__nv_bfloat16*)pool;
#pragma unroll
    for (int pass = 0; pass < 2; pass++) {
        __syncthreads();
#pragma unroll
        for (int i = 0; i < 4; i++)
#pragma unroll
            for (int j = 0; j < 4; j++)
                tb[(tx * 4 + j) * 72 + ty * 4 + i] = pass ? l4[i][j] : h4[i][j];
        __syncthreads();
        __nv_bfloat16* gp = pass ? g_ZTlo : g_ZThi;
#pragma unroll
        for (int k = 0; k < 2; k++) {
            int idx = tid + k * 256;
            int c_loc = idx >> 3;
            int r8 = (idx & 7) * 8;
            *(uint4*)&gp[(long)(col0 + c_loc) * NN + row0 + r8] =
                *(uint4*)&tb[c_loc * 72 + r8];
        }
    }
}

// ---------------------------------------------------------------------------
__device__ __forceinline__ void copy_tile_z(__nv_bfloat16* __restrict__ dst,
                                            const __nv_bfloat16* __restrict__ src,
                                            int tid) {
#pragma unroll
    for (int i = 0; i < 8; i++) {
        int idx = tid + i * 256;
        int row = idx >> 4;
        int c8 = (idx & 15) * 8;
        *(uint4*)&dst[row * PZ + c8] = *(const uint4*)&src[(long)row * HID + c8];
    }
}

// issue async copy of one 128x64 Zt tile pair (hi+lo) into buffer buf (0..2)
__device__ __forceinline__ void issue_zt(uint32_t smb, int buf, int m0, int tid) {
    const __nv_bfloat16* gh = g_ZThi + m0;
    const __nv_bfloat16* gl = g_ZTlo + m0;
    const uint32_t dH = smb + ZT_E(buf, 0) * 2;
    const uint32_t dL = smb + ZT_E(buf, 1) * 2;
#pragma unroll
    for (int i = 0; i < 4; i++) {
        int idx = tid + i * 256;
        int row = idx >> 3;
        int c8 = (idx & 7) * 8;
        uint32_t so = (uint32_t)(row * PT + c8) * 2;
        long go = (long)row * NN + c8;
        cp16(dH + so, gh + go);
        cp16(dL + so, gl + go);
    }
}

// ---------------------------------------------------------------------------
// Phase 2: persistent balanced scheduling over 8192 (rowblock, coltile) units.
// 148 CTAs, contiguous ranges (<=56 units, <=2 rowblock segments each).
// Register-resident S (FA2 style): warp owns 16 S-rows x 64-col tile; S acc
// -> relu/split/pack in regs -> A-operand of GEMM2. out/rowsum partials flush
// per segment via atomics.
// ---------------------------------------------------------------------------
__global__ __launch_bounds__(256, 1) void k_pass2(float* __restrict__ A) {
    extern __shared__ __nv_bfloat16 sm[];
    const uint32_t smb = smem_u32(sm);
    const int tid = threadIdx.x;
    const int wid = tid >> 5, lane = tid & 31;
    const int g = lane >> 2, tq = lane & 3;
    const int l15 = lane & 15;
    const int hi8 = (lane >> 4) * 8;

    int gid = (int)(((long)blockIdx.x * NTILE) / NCTA);
    const int gend = (int)(((long)(blockIdx.x + 1) * NTILE) / NCTA);

    const uint32_t a1H = smb + (ZNH_E + (wid * 16 + l15) * PZ + hi8) * 2;
    const uint32_t a1L = smb + (ZNL_E + (wid * 16 + l15) * PZ + hi8) * 2;
    const uint32_t b2off =
        (uint32_t)((((lane & 7) + ((lane >> 4) & 1) * 8) * PT +
                    ((lane >> 3) & 1) * 8) * 2);

    while (gid < gend) {
        const int rb = gid >> 7;
        const int segEnd = min(gend, (rb + 1) << 7);
        const int segLen = segEnd - gid;
        const int n0 = rb << 7;

        // guard: prior segment's warps all done reading Zt/Zn before overwrite
        __syncthreads();

        copy_tile_z(sm + ZNH_E, g_Zhi + (long)n0 * HID, tid);
        copy_tile_z(sm + ZNL_E, g_Zlo + (long)n0 * HID, tid);
        issue_zt(smb, 0, ((gid) & 127) * 64, tid);
        CP_COMMIT();
        if (segLen > 1) {
            issue_zt(smb, 1, ((gid + 1) & 127) * 64, tid);
            CP_COMMIT();
        }
        __syncthreads();

        // resident Zn fragments for this rowblock
        uint32_t rAH[8][4], rAL[8][4];
#pragma unroll
        for (int k8 = 0; k8 < 8; k8++) {
            ldsm_x4(rAH[k8], a1H + (k8 * 16) * 2);
            ldsm_x4(rAL[k8], a1L + (k8 * 16) * 2);
        }

        float oacc[16][4] = {};
        float rs0 = 0.0f, rs1 = 0.0f;

        for (int i = 0; i < segLen; i++) {
            const int cur = i % 3;
            const int m0 = ((gid + i) & 127) * 64;
            if (i + 1 < segLen) CP_WAIT1(); else CP_WAIT0();
            __syncthreads();  // Zt[cur] ready; slot (i+2)%3 free
            if (i + 2 < segLen) {
                issue_zt(smb, (i + 2) % 3, ((gid + i + 2) & 127) * 64, tid);
                CP_COMMIT();
            }

            const uint32_t ztH = smb + ZT_E(cur, 0) * 2;
            const uint32_t ztL = smb + ZT_E(cur, 1) * 2;
            const uint32_t b1H = ztH + (uint32_t)(l15 * PT + hi8) * 2;
            const uint32_t b1L = ztL + (uint32_t)(l15 * PT + hi8) * 2;

            // ---- GEMM1: S[16x64] = Zn(split) @ Zt(split) ----
            float cacc[8][4] = {};
#pragma unroll
            for (int k8 = 0; k8 < 8; k8++) {
                uint32_t bH[4][4], bL[4][4];
#pragma unroll
                for (int nc = 0; nc < 4; nc++) {
                    ldsm_x4t(bH[nc], b1H + (uint32_t)(k8 * 16 * PT + nc * 16) * 2);
                    ldsm_x4t(bL[nc], b1L + (uint32_t)(k8 * 16 * PT + nc * 16) * 2);
                }
#pragma unroll
                for (int nc = 0; nc < 4; nc++) {
                    mma16816(cacc[2 * nc], rAH[k8], &bH[nc][0]);
                    mma16816(cacc[2 * nc + 1], rAH[k8], &bH[nc][2]);
                    mma16816(cacc[2 * nc], rAH[k8], &bL[nc][0]);
                    mma16816(cacc[2 * nc + 1], rAH[k8], &bL[nc][2]);
                    mma16816(cacc[2 * nc], rAL[k8], &bH[nc][0]);
                    mma16816(cacc[2 * nc + 1], rAL[k8], &bH[nc][2]);
                }
            }

            // ---- epilogue in regs: relu, rowsum, A store, pack S frags ----
            uint32_t aSH[4][4], aSL[4][4];
#pragma unroll
            for (int nf = 0; nf < 8; nf++) {
                float* c = cacc[nf];
                float v0 = fmaxf(c[0], 0.f), v1 = fmaxf(c[1], 0.f);
                float v2 = fmaxf(c[2], 0.f), v3 = fmaxf(c[3], 0.f);
                rs0 += v0 + v1;
                rs1 += v2 + v3;
                const int lr = wid * 16 + g;
                const int lc = nf * 8 + 2 * tq;
                stcs2(&A[(long)(n0 + lr) * NN + m0 + lc], v0, v1);
                stcs2(&A[(long)(n0 + lr + 8) * NN + m0 + lc], v2, v3);
                float h0 = __bfloat162float(__float2bfloat16(v0));
                float h1 = __bfloat162float(__float2bfloat16(v1));
                float h2 = __bfloat162float(__float2bfloat16(v2));
                float h3 = __bfloat162float(__float2bfloat16(v3));
                const int j = nf >> 1, half = (nf & 1) * 2;
                aSH[j][half + 0] = pack_bf2(v0, v1);
                aSH[j][half + 1] = pack_bf2(v2, v3);
                aSL[j][half + 0] = pack_bf2(v0 - h0, v1 - h1);
                aSL[j][half + 1] = pack_bf2(v2 - h2, v3 - h3);
            }

            // ---- GEMM2: out[16x128] += S(frag, split) @ Zt-as-B(split) ----
#pragma unroll
            for (int j = 0; j < 4; j++) {
#pragma unroll
                for (int nh = 0; nh < 8; nh++) {
                    uint32_t bH2[4], bL2[4];
                    const uint32_t boff = b2off + (uint32_t)(nh * 16 * PT + j * 16) * 2;
                    ldsm_x4(bH2, ztH + boff);
                    ldsm_x4(bL2, ztL + boff);
                    mma16816(oacc[2 * nh], aSH[j], &bH2[0]);
                    mma16816(oacc[2 * nh + 1], aSH[j], &bH2[2]);
                    mma16816(oacc[2 * nh], aSH[j], &bL2[0]);
                    mma16816(oacc[2 * nh + 1], aSH[j], &bL2[2]);
                    mma16816(oacc[2 * nh], aSL[j], &bH2[0]);
                    mma16816(oacc[2 * nh + 1], aSL[j], &bH2[2]);
                }
            }
        }

        // ---- segment flush: rowsum + out partial via atomics ----
        rs0 += __shfl_xor_sync(~0u, rs0, 1);
        rs0 += __shfl_xor_sync(~0u, rs0, 2);
        rs1 += __shfl_xor_sync(~0u, rs1, 1);
        rs1 += __shfl_xor_sync(~0u, rs1, 2);
        if (tq == 0) {
            atomicAdd(&g_rs[n0 + wid * 16 + g], rs0);
            atomicAdd(&g_rs[n0 + wid * 16 + 8 + g], rs1);
        }
        const int r0 = n0 + wid * 16 + g;
#pragma unroll
        for (int o = 0; o < 16; o++) {
            const int col = o * 8 + 2 * tq;
            atomicAdd(&g_outp[r0 * HID + col], oacc[o][0]);
            atomicAdd(&g_outp[r0 * HID + col + 1], oacc[o][1]);
            atomicAdd(&g_outp[(r0 + 8) * HID + col], oacc[o][2]);
            atomicAdd(&g_outp[(r0 + 8) * HID + col + 1], oacc[o][3]);
        }

        gid = segEnd;
    }
}

// ---------------------------------------------------------------------------
// Phase 3a: A *= 1/(rowsum+1e-6); streaming, 8 independent float4 per thread
// ---------------------------------------------------------------------------
__global__ __launch_bounds__(256) void k_norm_A(float* __restrict__ A) {
    const long i0 = (long)blockIdx.x * 2048 + threadIdx.x;
    float4 v[8];
    float inv[8];
#pragma unroll
    for (int j = 0; j < 8; j++) {
        long i = i0 + j * 256;
        v[j] = __ldcs(&((const float4*)A)[i]);
        int r = (int)(i >> 11);
        inv[j] = 1.0f / (g_rs[r] + 1e-6f);
    }
#pragma unroll
    for (int j = 0; j < 8; j++) {
        long i = i0 + j * 256;
        float4 w = v[j];
        w.x *= inv[j]; w.y *= inv[j]; w.z *= inv[j]; w.w *= inv[j];
        __stcs(&((float4*)A)[i], w);
    }
}

// ---------------------------------------------------------------------------
// Phase 3b: out = partial * inv(rowsum)
// ---------------------------------------------------------------------------
__global__ void k_norm_out(float* __restrict__ o) {
    int i = blockIdx.x * blockDim.x + threadIdx.x;
    if (i < NN * HID) {
        int r = i >> 7;
        o[i] = g_outp[i] * (1.0f / (g_rs[r] + 1e-6f));
    }
}

// ---------------------------------------------------------------------------
extern "C" void kernel_launch(void* const* d_in, const int* in_sizes, int n_in,
                              void* d_out, int out_size) {
    const float* X = (const float*)d_in[0];
    const float* W = (const float*)d_in[1];
    float* out = (float*)d_out;
    float* A = out + NN * HID;

    k_gemm_z<<<dim3(NN / 64, HID / 64), 256>>>(X, W);

    cudaFuncSetAttribute(k_pass2, cudaFuncAttributeMaxDynamicSharedMemorySize,
                         SMEM_BYTES);
    k_pass2<<<NCTA, 256, SMEM_BYTES>>>(A);

    k_norm_A<<<8192, 256>>>(A);
    k_norm_out<<<(NN * HID + 255) / 256, 256>>>(out);
}